// round 14
// baseline (speedup 1.0000x reference)
#include <cuda_runtime.h>
#include <cuda_bf16.h>
#include <math.h>
#include <stdint.h>

// Problem constants
#define BB   16
#define CC   1024
#define HH   32
#define WW   32
#define NE   256
#define NPIX (BB*HH*WW)          // 16384
#define OUT_ELEMS (BB*CC*HH*WW)  // 16777216
#define LOSS_OFF  OUT_ELEMS
#define PERP_OFF  (OUT_ELEMS+1)
#define IDX_OFF   (OUT_ELEMS+2)

#define KCHUNK 16
#define NCHUNK (CC/KCHUNK)       // 64

// Scratch (no cudaMalloc allowed)
__device__ float g_code_out[CC*NE];   // TRANSPOSED: [o][j]
__device__ float g_ee2[NE];
__device__ int   g_idx[NPIX];
__device__ int   g_counts[NE];
__device__ float g_loss_sum;
// e splits (tf32 bit patterns), B-fragment order:
// [split(2)][chunk(64)][kt(2)][nt(32)][lane(32)][slot(2)] = 2 MB
#define CHW 4096   // words per (split,chunk) plane
__device__ __align__(16) float g_es2[2*NCHUNK*CHW];

// ---------------------------------------------------------------------------
__device__ __forceinline__ uint32_t f2tf32(float x) {
    uint32_t r;
    asm("cvt.rna.tf32.f32 %0, %1;" : "=r"(r) : "f"(x));
    return r;
}
__device__ __forceinline__ void mma_tf32(float c[4],
    uint32_t a0, uint32_t a1, uint32_t a2, uint32_t a3,
    uint32_t b0, uint32_t b1)
{
    asm volatile(
        "mma.sync.aligned.m16n8k8.row.col.f32.tf32.tf32.f32 "
        "{%0,%1,%2,%3}, {%4,%5,%6,%7}, {%8,%9}, {%0,%1,%2,%3};"
        : "+f"(c[0]), "+f"(c[1]), "+f"(c[2]), "+f"(c[3])
        : "r"(a0), "r"(a1), "r"(a2), "r"(a3), "r"(b0), "r"(b1));
}
__device__ __forceinline__ uint32_t smem_u32(const void* p) {
    uint32_t a;
    asm("{ .reg .u64 t; cvta.to.shared.u64 t, %1; cvt.u32.u64 %0, t; }" : "=r"(a) : "l"(p));
    return a;
}
__device__ __forceinline__ void cp_async16(uint32_t saddr, const void* g) {
    asm volatile("cp.async.cg.shared.global [%0], [%1], 16;" :: "r"(saddr), "l"(g));
}
#define CP_COMMIT() asm volatile("cp.async.commit_group;")
#define CP_WAIT0()  asm volatile("cp.async.wait_group 0;" ::: "memory")

// ---------------------------------------------------------------------------
// Kernel 0: |e_j|^2 + reset + 2-way tf32 split of emb (B-fragment permuted)
// ---------------------------------------------------------------------------
__global__ void k_prep(const float* __restrict__ emb) {
    int j = blockIdx.x, t = threadIdx.x;   // 256 x 256
    int nt = j >> 3;
    float s = 0.f;
    #pragma unroll
    for (int i = 0; i < 4; i++) {
        int k = t*4 + i;
        float x = emb[(size_t)j*CC + k];
        s = fmaf(x, x, s);
        uint32_t hi = f2tf32(x);
        uint32_t lo = f2tf32(x - __uint_as_float(hi));
        int ch = k >> 4, kk4 = k & 15;
        int kt = kk4 >> 3, kk = kk4 & 7;
        int lane = (j & 7)*4 + (kk & 3);
        int slot = kk >> 2;
        size_t off = (((size_t)kt*32 + nt)*32 + lane)*2 + slot;
        ((uint32_t*)g_es2)[(size_t)ch*CHW + off] = hi;
        ((uint32_t*)g_es2)[(size_t)(NCHUNK + ch)*CHW + off] = lo;
    }
    __shared__ float red[256];
    red[t] = s; __syncthreads();
    for (int st = 128; st > 0; st >>= 1) { if (t < st) red[t] += red[t+st]; __syncthreads(); }
    if (t == 0) { g_ee2[j] = red[0]; g_counts[j] = 0; if (j == 0) g_loss_sum = 0.f; }
}

// ---------------------------------------------------------------------------
// Kernel 1: code_out[o][j] = emb[j].conv_w[o] + b[o]  (fp32, transposed out)
// Runs CONCURRENTLY on a forked stream.
// ---------------------------------------------------------------------------
__global__ void __launch_bounds__(256) k_codeout(
    const float* __restrict__ emb, const float* __restrict__ w,
    const float* __restrict__ bias)
{
    __shared__ float es[16][64];
    __shared__ float ws[16][64];
    int t  = threadIdx.x;
    int o0 = blockIdx.x * 64, j0 = blockIdx.y * 64;
    int rl = t & 63, grp = t >> 6;
    int tol = t & 15, tjl = t >> 4;
    float acc[4][4] = {};
    for (int k0 = 0; k0 < CC; k0 += 16) {
        float4 fe = *(const float4*)&emb[(size_t)(j0+rl)*CC + k0 + grp*4];
        float4 fw = *(const float4*)&w  [(size_t)(o0+rl)*CC + k0 + grp*4];
        es[grp*4+0][rl]=fe.x; es[grp*4+1][rl]=fe.y; es[grp*4+2][rl]=fe.z; es[grp*4+3][rl]=fe.w;
        ws[grp*4+0][rl]=fw.x; ws[grp*4+1][rl]=fw.y; ws[grp*4+2][rl]=fw.z; ws[grp*4+3][rl]=fw.w;
        __syncthreads();
        #pragma unroll
        for (int kk = 0; kk < 16; kk++) {
            float er[4], wr[4];
            #pragma unroll
            for (int i = 0; i < 4; i++) { er[i] = es[kk][tjl*4+i]; wr[i] = ws[kk][tol*4+i]; }
            #pragma unroll
            for (int jy = 0; jy < 4; jy++)
                #pragma unroll
                for (int ox = 0; ox < 4; ox++)
                    acc[jy][ox] = fmaf(er[jy], wr[ox], acc[jy][ox]);
        }
        __syncthreads();
    }
    #pragma unroll
    for (int jy = 0; jy < 4; jy++)
        #pragma unroll
        for (int ox = 0; ox < 4; ox++)
            g_code_out[(size_t)(o0+tol*4+ox)*NE + (j0+tjl*4+jy)] = acc[jy][ox] + bias[o0+tol*4+ox];
}

// ---------------------------------------------------------------------------
// Kernel 2: 3xTF32 warp-MMA argmin. 256 CTAs x 256 thr, 2 CTAs/SM.
// CTA tile M=64 x N=256, K=1024 in 64 chunks of 16. Warp grid 2(M)x4(N),
// warp tile 32x64. Two resident CTAs interleave across barrier shadows.
// ---------------------------------------------------------------------------
// Per buffer: A = 2 planes x 1024 fl (8KB), B = 2 splits x 4096 fl (32KB)
#define A_BUF 2048
#define B_BUF 8192
#define DYN_SMEM ((2*A_BUF + 2*B_BUF) * 4)   // 80 KB -> 2 CTAs/SM

__global__ void __launch_bounds__(256, 2) k_argmin_tc(
    const float* __restrict__ z, float* __restrict__ out)
{
    extern __shared__ float smem[];
    float* As = smem;                  // 2 x A_BUF
    float* Bs = smem + 2*A_BUF;        // 2 x B_BUF
    __shared__ unsigned long long sKey[64];
    __shared__ float redf[256];
    __shared__ float ee2_s[NE];

    int t = threadIdx.x, lane = t & 31, w = t >> 5;
    int wm = w >> 2, wn = w & 3;         // warp grid 2 (M) x 4 (N)
    int g = lane >> 2, tig = lane & 3;
    int cta = blockIdx.x;                // 256 CTAs, 64 pixels each
    int bb = cta >> 4;
    int p0 = (cta & 15) * 64;

    if (t < 64) sKey[t] = ~0ull;
    ee2_s[t] = g_ee2[t];

    uint32_t bs_addr = smem_u32(Bs);

    float acc[2][8][4];
    #pragma unroll
    for (int m = 0; m < 2; m++)
        #pragma unroll
        for (int n = 0; n < 8; n++)
            #pragma unroll
            for (int q = 0; q < 4; q++) acc[m][n][q] = 0.f;

    float zsq = 0.f;
    const float* zb = z + (size_t)bb*(CC*1024) + p0;

    // A tiles: 8 (kt2 x mt4) per chunk; warps 0-7 stage one tile each.
    int kt_a = w >> 2, mt_a = w & 3;     // valid for w<8
    float zr[4];

    auto ld_a = [&](int ch) {
        if (w < 8) {
            const float* zp = zb + (size_t)(ch*KCHUNK + kt_a*8 + tig)*1024 + mt_a*16 + g;
            zr[0] = zp[0];
            zr[1] = zp[8];
            zr[2] = zp[4*1024];
            zr[3] = zp[4*1024 + 8];
        }
    };
    auto cvt_a = [&](int buf) {
        if (w < 8) {
            float v0 = zr[0], v1 = zr[1], v2 = zr[2], v3 = zr[3];
            zsq = fmaf(v0,v0,zsq); zsq = fmaf(v1,v1,zsq);
            zsq = fmaf(v2,v2,zsq); zsq = fmaf(v3,v3,zsq);
            uint32_t h0=f2tf32(v0), h1=f2tf32(v1), h2=f2tf32(v2), h3=f2tf32(v3);
            uint32_t l0=f2tf32(v0-__uint_as_float(h0));
            uint32_t l1=f2tf32(v1-__uint_as_float(h1));
            uint32_t l2=f2tf32(v2-__uint_as_float(h2));
            uint32_t l3=f2tf32(v3-__uint_as_float(h3));
            int base = buf*A_BUF + ((kt_a*4 + mt_a)*32 + lane)*4;
            *(uint4*)&As[base]        = make_uint4(h0,h1,h2,h3);
            *(uint4*)&As[base + 1024] = make_uint4(l0,l1,l2,l3);
        }
    };
    auto issue_b = [&](int ch, int buf) {
        const float* s0 = g_es2 + (size_t)ch*CHW;
        const float* s1 = g_es2 + (size_t)(NCHUNK + ch)*CHW;
        uint32_t d0 = bs_addr + (buf*B_BUF)*4;
        uint32_t d1 = d0 + 4096*4;
        #pragma unroll
        for (int q = 0; q < 4; q++) {
            int idx = t + 256*q;
            cp_async16(d0 + idx*16, (const void*)(s0 + idx*4));
            cp_async16(d1 + idx*16, (const void*)(s1 + idx*4));
        }
    };
    auto compute = [&](int buf, int kt) {
        uint4 ah[2], al[2];
        #pragma unroll
        for (int m = 0; m < 2; m++) {
            int base = buf*A_BUF + ((kt*4 + wm*2 + m)*32 + lane)*4;
            ah[m] = *(const uint4*)&As[base];
            al[m] = *(const uint4*)&As[base + 1024];
        }
        #pragma unroll
        for (int n = 0; n < 8; n++) {
            int bbase = buf*B_BUF + ((kt*32 + wn*8 + n)*32 + lane)*2;
            uint2 bh = *(const uint2*)&Bs[bbase];
            uint2 bl = *(const uint2*)&Bs[bbase + 4096];
            #pragma unroll
            for (int m = 0; m < 2; m++) {
                mma_tf32(acc[m][n], ah[m].x, ah[m].y, ah[m].z, ah[m].w, bh.x, bh.y);
                mma_tf32(acc[m][n], ah[m].x, ah[m].y, ah[m].z, ah[m].w, bl.x, bl.y);
                mma_tf32(acc[m][n], al[m].x, al[m].y, al[m].z, al[m].w, bh.x, bh.y);
            }
        }
    };

    // --- prologue: stage chunk 0 into buffer 0 ---
    issue_b(0, 0);
    CP_COMMIT();
    ld_a(0);
    cvt_a(0);
    CP_WAIT0();
    __syncthreads();

    // --- main pipeline ---
    for (int ch = 0; ch < NCHUNK; ch++) {
        int buf = ch & 1, nbuf = buf ^ 1;
        bool more = (ch + 1 < NCHUNK);
        if (more) {
            issue_b(ch + 1, nbuf);
            CP_COMMIT();
            ld_a(ch + 1);
        }
        compute(buf, 0);
        if (more) cvt_a(nbuf);
        compute(buf, 1);
        if (more) CP_WAIT0();
        __syncthreads();
    }

    // --- epilogue: per-thread min over its 16 codes for each of 4 pixels ---
    #pragma unroll
    for (int m = 0; m < 2; m++) {
        unsigned long long b0 = ~0ull, b1 = ~0ull;
        #pragma unroll
        for (int n = 0; n < 8; n++) {
            int j0 = wn*64 + n*8 + tig*2;
            #pragma unroll
            for (int q = 0; q < 2; q++) {
                float s_lo = ee2_s[j0+q] - 2.f*acc[m][n][q];     // pixel row g
                float s_hi = ee2_s[j0+q] - 2.f*acc[m][n][q+2];   // pixel row g+8
                unsigned u0 = __float_as_uint(s_lo);
                u0 = (u0 & 0x80000000u) ? ~u0 : (u0 | 0x80000000u);
                unsigned long long k0 = ((unsigned long long)u0 << 32) | (unsigned)(j0+q);
                b0 = (k0 < b0) ? k0 : b0;
                unsigned u1 = __float_as_uint(s_hi);
                u1 = (u1 & 0x80000000u) ? ~u1 : (u1 | 0x80000000u);
                unsigned long long k1 = ((unsigned long long)u1 << 32) | (unsigned)(j0+q);
                b1 = (k1 < b1) ? k1 : b1;
            }
        }
        int prow = wm*32 + m*16 + g;
        atomicMin(&sKey[prow], b0);
        atomicMin(&sKey[prow + 8], b1);
    }
    __syncthreads();

    float dmin = 0.f;
    if (t < 64) {
        unsigned long long k = sKey[t];
        int j = (int)(k & 0xFFFFFFFFu);
        unsigned u = (unsigned)(k >> 32);
        unsigned fb = (u & 0x80000000u) ? (u & 0x7FFFFFFFu) : ~u;
        dmin = __uint_as_float(fb);
        int n = cta*64 + t;
        g_idx[n] = j;
        atomicAdd(&g_counts[j], 1);
        out[IDX_OFF + n] = (float)j;
    }

    redf[t] = zsq + dmin;
    __syncthreads();
    for (int st = 128; st > 0; st >>= 1) { if (t < st) redf[t] += redf[t+st]; __syncthreads(); }
    if (t == 0) atomicAdd(&g_loss_sum, redf[0]);
}

// ---------------------------------------------------------------------------
// Kernel 3: gather-scatter + fused finalize (block 0).
// ---------------------------------------------------------------------------
__global__ void __launch_bounds__(256) k_scatter(float* __restrict__ out)
{
    int bid = blockIdx.x;
    int b  = bid >> 5, oc = bid & 31;
    __shared__ int   idx_s[1024];
    __shared__ float ct[32*256];
    __shared__ float fred[256];
    int t = threadIdx.x;

    if (bid == 0) {   // fused finalize: loss + perplexity
        float em = (float)g_counts[t] / (float)NPIX;
        fred[t] = em * logf(em + 1e-10f);
        __syncthreads();
        for (int st = 128; st > 0; st >>= 1) { if (t < st) fred[t] += fred[t+st]; __syncthreads(); }
        if (t == 0) {
            out[LOSS_OFF] = 1.25f * g_loss_sum / (float)OUT_ELEMS;
            out[PERP_OFF] = expf(-fred[0]);
        }
    }

    #pragma unroll
    for (int r = 0; r < 4; r++) idx_s[t + 256*r] = g_idx[b*1024 + t + 256*r];
    const float4* src = (const float4*)(g_code_out + (size_t)oc*32*NE);
    float4* dst = (float4*)ct;
    #pragma unroll
    for (int r = 0; r < 8; r++) dst[t + 256*r] = src[t + 256*r];
    __syncthreads();
    int warp = t >> 5, lane = t & 31;
    float* ob = out + (size_t)b*(CC*HH*WW) + (size_t)oc*32*(HH*WW);
    #pragma unroll
    for (int q = 0; q < 4; q++) {
        int o = warp*4 + q;
        const float* crow = &ct[o*NE];
        #pragma unroll
        for (int p0 = 0; p0 < 1024; p0 += 128) {
            int4 j4 = *(const int4*)&idx_s[p0 + lane*4];
            float4 v;
            v.x = crow[j4.x]; v.y = crow[j4.y]; v.z = crow[j4.z]; v.w = crow[j4.w];
            *(float4*)&ob[(size_t)o*(HH*WW) + p0 + lane*4] = v;
        }
    }
}

// ---------------------------------------------------------------------------
// Launch: fork k_codeout onto a side stream, join before k_scatter.
// ---------------------------------------------------------------------------
extern "C" void kernel_launch(void* const* d_in, const int* in_sizes, int n_in,
                              void* d_out, int out_size) {
    const float* z      = (const float*)d_in[0];
    const float* emb    = (const float*)d_in[1];
    const float* conv_w = (const float*)d_in[2];
    const float* conv_b = (const float*)d_in[3];
    float* out = (float*)d_out;

    static cudaStream_t s_side = 0;
    static cudaEvent_t  ev_fork = 0, ev_join = 0;
    if (s_side == 0) {
        cudaStreamCreateWithFlags(&s_side, cudaStreamNonBlocking);
        cudaEventCreateWithFlags(&ev_fork, cudaEventDisableTiming);
        cudaEventCreateWithFlags(&ev_join, cudaEventDisableTiming);
        cudaFuncSetAttribute(k_argmin_tc, cudaFuncAttributeMaxDynamicSharedMemorySize, DYN_SMEM);
    }

    cudaEventRecord(ev_fork, 0);
    cudaStreamWaitEvent(s_side, ev_fork, 0);

    k_codeout<<<dim3(CC/64, NE/64), 256, 0, s_side>>>(emb, conv_w, conv_b);
    cudaEventRecord(ev_join, s_side);

    k_prep<<<NE, 256>>>(emb);
    k_argmin_tc<<<NPIX/64, 256, DYN_SMEM>>>(z, out);

    cudaStreamWaitEvent(0, ev_join, 0);
    k_scatter<<<BB*HH, 256>>>(out);
}

// round 17
// speedup vs baseline: 1.3941x; 1.3941x over previous
#include <cuda_runtime.h>
#include <cuda_fp16.h>
#include <math.h>
#include <stdint.h>

// Problem constants
#define BB   16
#define CC   1024
#define HH   32
#define WW   32
#define NE   256
#define NPIX (BB*HH*WW)          // 16384
#define OUT_ELEMS (BB*CC*HH*WW)  // 16777216
#define LOSS_OFF  OUT_ELEMS
#define PERP_OFF  (OUT_ELEMS+1)
#define IDX_OFF   (OUT_ELEMS+2)

#define KCHUNK 32
#define NCHUNK (CC/KCHUNK)       // 32
#define ZSC 64.0f                // scale keeps fp16 lo-split out of denormals
#define INV_SC2 (1.0f/4096.0f)   // 1/(ZSC*ZSC)

// Scratch (no cudaMalloc allowed)
__device__ float g_code_out[CC*NE];   // TRANSPOSED: [o][j]
__device__ float g_ee2[NE];
__device__ int   g_idx[NPIX];
__device__ int   g_counts[NE];
__device__ float g_loss_sum;
// e splits (fp16 pairs packed in u32), m16n8k16 B-fragment order:
// [split(2)][chunk(32)][kt(2)][nt(32)][lane(32)][slot(2)] words = 1 MB
#define CHW 4096   // words per (split,chunk) plane
__device__ __align__(16) uint32_t g_es2[2*NCHUNK*CHW];

// ---------------------------------------------------------------------------
__device__ __forceinline__ void hsplit(float x, uint16_t& h, uint16_t& l) {
    __half hh = __float2half_rn(x);
    float r = x - __half2float(hh);
    __half ll = __float2half_rn(r);
    h = __half_as_ushort(hh);
    l = __half_as_ushort(ll);
}
__device__ __forceinline__ void mma_f16(float c[4], uint4 a, uint2 b) {
    asm volatile(
        "mma.sync.aligned.m16n8k16.row.col.f32.f16.f16.f32 "
        "{%0,%1,%2,%3}, {%4,%5,%6,%7}, {%8,%9}, {%0,%1,%2,%3};"
        : "+f"(c[0]), "+f"(c[1]), "+f"(c[2]), "+f"(c[3])
        : "r"(a.x), "r"(a.y), "r"(a.z), "r"(a.w), "r"(b.x), "r"(b.y));
}
__device__ __forceinline__ uint32_t smem_u32(const void* p) {
    uint32_t a;
    asm("{ .reg .u64 t; cvta.to.shared.u64 t, %1; cvt.u32.u64 %0, t; }" : "=r"(a) : "l"(p));
    return a;
}
__device__ __forceinline__ void cp_async16(uint32_t saddr, const void* g) {
    asm volatile("cp.async.cg.shared.global [%0], [%1], 16;" :: "r"(saddr), "l"(g));
}
#define CP_COMMIT() asm volatile("cp.async.commit_group;")
#define CP_WAIT0()  asm volatile("cp.async.wait_group 0;" ::: "memory")

// ---------------------------------------------------------------------------
// Kernel 0: |e_j|^2 + reset + 2-way fp16 split of 64*emb (B-fragment order)
// B frag m16n8k16: n = nt*8 + (lane>>2); b0 halves k = kt*16 + 2*t4 + {0,1};
// b1 halves k = kt*16 + 2*t4 + {8,9};  lane = (j&7)*4 + t4.
// ---------------------------------------------------------------------------
__global__ void k_prep(const float* __restrict__ emb) {
    int j = blockIdx.x, t = threadIdx.x;   // 256 x 256
    int nt = j >> 3, gg = j & 7;
    float s = 0.f;
    #pragma unroll
    for (int i = 0; i < 4; i += 2) {
        int k = t*4 + i;                    // even; pair (k, k+1) shares a word
        float x0 = emb[(size_t)j*CC + k];
        float x1 = emb[(size_t)j*CC + k + 1];
        s = fmaf(x0, x0, s); s = fmaf(x1, x1, s);
        uint16_t h0, l0, h1, l1;
        hsplit(x0 * ZSC, h0, l0);
        hsplit(x1 * ZSC, h1, l1);
        uint32_t wh = ((uint32_t)h1 << 16) | h0;
        uint32_t wl = ((uint32_t)l1 << 16) | l0;
        int ch = k >> 5, kk = k & 31;
        int kt = kk >> 4, r = kk & 15;
        int slot = r >> 3, t4 = (r & 7) >> 1;
        int lane = gg*4 + t4;
        size_t off = ((size_t)(kt*32 + nt)*32 + lane)*2 + slot;
        g_es2[(size_t)ch*CHW + off] = wh;
        g_es2[(size_t)(NCHUNK + ch)*CHW + off] = wl;
    }
    __shared__ float red[256];
    red[t] = s; __syncthreads();
    for (int st = 128; st > 0; st >>= 1) { if (t < st) red[t] += red[t+st]; __syncthreads(); }
    if (t == 0) { g_ee2[j] = red[0]; g_counts[j] = 0; if (j == 0) g_loss_sum = 0.f; }
}

// ---------------------------------------------------------------------------
// Kernel 1: code_out[o][j] = emb[j].conv_w[o] + b[o]  (fp32, transposed out)
// Runs CONCURRENTLY on a forked stream.
// ---------------------------------------------------------------------------
__global__ void __launch_bounds__(256) k_codeout(
    const float* __restrict__ emb, const float* __restrict__ w,
    const float* __restrict__ bias)
{
    __shared__ float es[16][64];
    __shared__ float ws[16][64];
    int t  = threadIdx.x;
    int o0 = blockIdx.x * 64, j0 = blockIdx.y * 64;
    int rl = t & 63, grp = t >> 6;
    int tol = t & 15, tjl = t >> 4;
    float acc[4][4] = {};
    for (int k0 = 0; k0 < CC; k0 += 16) {
        float4 fe = *(const float4*)&emb[(size_t)(j0+rl)*CC + k0 + grp*4];
        float4 fw = *(const float4*)&w  [(size_t)(o0+rl)*CC + k0 + grp*4];
        es[grp*4+0][rl]=fe.x; es[grp*4+1][rl]=fe.y; es[grp*4+2][rl]=fe.z; es[grp*4+3][rl]=fe.w;
        ws[grp*4+0][rl]=fw.x; ws[grp*4+1][rl]=fw.y; ws[grp*4+2][rl]=fw.z; ws[grp*4+3][rl]=fw.w;
        __syncthreads();
        #pragma unroll
        for (int kk = 0; kk < 16; kk++) {
            float er[4], wr[4];
            #pragma unroll
            for (int i = 0; i < 4; i++) { er[i] = es[kk][tjl*4+i]; wr[i] = ws[kk][tol*4+i]; }
            #pragma unroll
            for (int jy = 0; jy < 4; jy++)
                #pragma unroll
                for (int ox = 0; ox < 4; ox++)
                    acc[jy][ox] = fmaf(er[jy], wr[ox], acc[jy][ox]);
        }
        __syncthreads();
    }
    #pragma unroll
    for (int jy = 0; jy < 4; jy++)
        #pragma unroll
        for (int ox = 0; ox < 4; ox++)
            g_code_out[(size_t)(o0+tol*4+ox)*NE + (j0+tjl*4+jy)] = acc[jy][ox] + bias[o0+tol*4+ox];
}

// ---------------------------------------------------------------------------
// Kernel 2: 3xFP16 (m16n8k16) warp-MMA argmin. 128 CTAs x 512 thr
// (16 warps, grid 4(M)x4(N); warp tile 32x64). KCHUNK=32 = 2 k16 steps.
// acc += zh*eh + zh*el + zl*eh on 64*z, 64*e; scores scale by 4096 (argmin
// invariant); dmin /= 4096 exactly. cp.async double-buffered.
// ---------------------------------------------------------------------------
// Per buffer: A = 2 splits x 16 tiles x 128 words (16KB), B = 2 x 4096 w (32KB)
#define A_BUF 4096
#define B_BUF 8192
#define DYN_SMEM ((2*A_BUF + 2*B_BUF) * 4)   // 96 KB

__global__ void __launch_bounds__(512, 1) k_argmin_tc(
    const float* __restrict__ z, float* __restrict__ out)
{
    extern __shared__ float smem[];
    float* As = smem;                  // 2 x A_BUF words
    float* Bs = smem + 2*A_BUF;        // 2 x B_BUF words
    __shared__ unsigned long long sKey[128];
    __shared__ float redf[512];
    __shared__ float ee2_s[NE];

    int t = threadIdx.x, lane = t & 31, w = t >> 5;
    int wm = w >> 2, wn = w & 3;         // warp grid 4 (M) x 4 (N)
    int g = lane >> 2, t4 = lane & 3;
    int cta = blockIdx.x;                // 128 CTAs
    int bb = cta >> 3;
    int p0 = (cta & 7) * 128;

    if (t < 128) sKey[t] = ~0ull;
    if (t < NE)  ee2_s[t] = g_ee2[t] * 4096.0f;   // pre-scaled

    uint32_t bs_addr = smem_u32(Bs);

    float acc[2][8][4];
    #pragma unroll
    for (int m = 0; m < 2; m++)
        #pragma unroll
        for (int n = 0; n < 8; n++)
            #pragma unroll
            for (int q = 0; q < 4; q++) acc[m][n][q] = 0.f;

    float zsq = 0.f;
    const float* zb = z + (size_t)bb*(CC*1024) + p0;

    // A tiles: 16 (kt2 x mt8) per chunk; warp w stages tile w.
    int kt_a = w >> 3, mt_a = w & 7;
    float zr[8];

    auto ld_a = [&](int ch) {
        const float* zp = zb + (size_t)(ch*KCHUNK + kt_a*16 + 2*t4)*1024 + mt_a*16 + g;
        zr[0] = zp[0];          zr[1] = zp[8];            // k+0: rows g, g+8
        zr[2] = zp[1024];       zr[3] = zp[1024 + 8];     // k+1
        zr[4] = zp[8*1024];     zr[5] = zp[8*1024 + 8];   // k+8
        zr[6] = zp[9*1024];     zr[7] = zp[9*1024 + 8];   // k+9
    };
    auto cvt_a = [&](int buf) {
        #pragma unroll
        for (int i = 0; i < 8; i++) zsq = fmaf(zr[i], zr[i], zsq);
        uint16_t h[8], l[8];
        #pragma unroll
        for (int i = 0; i < 8; i++) hsplit(zr[i] * ZSC, h[i], l[i]);
        // a0:(row g, k0|k1) a1:(g+8, k0|k1) a2:(g, k8|k9) a3:(g+8, k8|k9)
        uint4 ah = make_uint4(((uint32_t)h[2]<<16)|h[0], ((uint32_t)h[3]<<16)|h[1],
                              ((uint32_t)h[6]<<16)|h[4], ((uint32_t)h[7]<<16)|h[5]);
        uint4 al = make_uint4(((uint32_t)l[2]<<16)|l[0], ((uint32_t)l[3]<<16)|l[1],
                              ((uint32_t)l[6]<<16)|l[4], ((uint32_t)l[7]<<16)|l[5]);
        int base = buf*A_BUF + (kt_a*8 + mt_a)*128 + lane*4;
        *(uint4*)&As[base]        = ah;
        *(uint4*)&As[base + 2048] = al;
    };
    auto issue_b = [&](int ch, int buf) {
        const uint32_t* s0 = g_es2 + (size_t)ch*CHW;
        const uint32_t* s1 = g_es2 + (size_t)(NCHUNK + ch)*CHW;
        uint32_t d0 = bs_addr + (buf*B_BUF)*4;
        uint32_t d1 = d0 + 4096*4;
        #pragma unroll
        for (int q = 0; q < 2; q++) {
            int idx = t + 512*q;
            cp_async16(d0 + idx*16, (const void*)(s0 + idx*4));
            cp_async16(d1 + idx*16, (const void*)(s1 + idx*4));
        }
    };
    auto compute = [&](int buf, int kt) {
        uint4 ah[2], al[2];
        #pragma unroll
        for (int m = 0; m < 2; m++) {
            int base = buf*A_BUF + (kt*8 + wm*2 + m)*128 + lane*4;
            ah[m] = *(const uint4*)&As[base];
            al[m] = *(const uint4*)&As[base + 2048];
        }
        #pragma unroll
        for (int n = 0; n < 8; n++) {
            int nt = wn*8 + n;
            int bbase = buf*B_BUF + (kt*32 + nt)*64 + lane*2;
            uint2 bh = *(const uint2*)&Bs[bbase];
            uint2 bl = *(const uint2*)&Bs[bbase + 4096];
            #pragma unroll
            for (int m = 0; m < 2; m++) {
                mma_f16(acc[m][n], ah[m], bh);
                mma_f16(acc[m][n], ah[m], bl);
                mma_f16(acc[m][n], al[m], bh);
            }
        }
    };

    // --- prologue ---
    issue_b(0, 0);
    CP_COMMIT();
    ld_a(0);
    cvt_a(0);
    CP_WAIT0();
    __syncthreads();

    // --- main pipeline ---
    for (int ch = 0; ch < NCHUNK; ch++) {
        int buf = ch & 1, nbuf = buf ^ 1;
        bool more = (ch + 1 < NCHUNK);
        if (more) {
            issue_b(ch + 1, nbuf);
            CP_COMMIT();
            ld_a(ch + 1);
        }
        compute(buf, 0);
        if (more) cvt_a(nbuf);
        compute(buf, 1);
        if (more) CP_WAIT0();
        __syncthreads();
    }

    // --- epilogue: min over 16 codes per pixel (scaled scores) ---
    #pragma unroll
    for (int m = 0; m < 2; m++) {
        unsigned long long b0 = ~0ull, b1 = ~0ull;
        #pragma unroll
        for (int n = 0; n < 8; n++) {
            int j0 = wn*64 + n*8 + t4*2;
            #pragma unroll
            for (int q = 0; q < 2; q++) {
                float s_lo = ee2_s[j0+q] - 2.f*acc[m][n][q];     // pixel row g
                float s_hi = ee2_s[j0+q] - 2.f*acc[m][n][q+2];   // pixel row g+8
                unsigned u0 = __float_as_uint(s_lo);
                u0 = (u0 & 0x80000000u) ? ~u0 : (u0 | 0x80000000u);
                unsigned long long k0 = ((unsigned long long)u0 << 32) | (unsigned)(j0+q);
                b0 = (k0 < b0) ? k0 : b0;
                unsigned u1 = __float_as_uint(s_hi);
                u1 = (u1 & 0x80000000u) ? ~u1 : (u1 | 0x80000000u);
                unsigned long long k1 = ((unsigned long long)u1 << 32) | (unsigned)(j0+q);
                b1 = (k1 < b1) ? k1 : b1;
            }
        }
        int prow = wm*32 + m*16 + g;
        atomicMin(&sKey[prow], b0);
        atomicMin(&sKey[prow + 8], b1);
    }
    __syncthreads();

    float dmin = 0.f;
    if (t < 128) {
        unsigned long long k = sKey[t];
        int j = (int)(k & 0xFFFFFFFFu);
        unsigned u = (unsigned)(k >> 32);
        unsigned fb = (u & 0x80000000u) ? (u & 0x7FFFFFFFu) : ~u;
        dmin = __uint_as_float(fb) * INV_SC2;     // exact power-of-2 unscale
        int n = cta*128 + t;
        g_idx[n] = j;
        atomicAdd(&g_counts[j], 1);
        out[IDX_OFF + n] = (float)j;
    }

    redf[t] = zsq + dmin;
    __syncthreads();
    for (int st = 256; st > 0; st >>= 1) { if (t < st) redf[t] += redf[t+st]; __syncthreads(); }
    if (t == 0) atomicAdd(&g_loss_sum, redf[0]);
}

// ---------------------------------------------------------------------------
// Kernel 3: gather-scatter + fused finalize (block 0).
// ---------------------------------------------------------------------------
__global__ void __launch_bounds__(256) k_scatter(float* __restrict__ out)
{
    int bid = blockIdx.x;
    int b  = bid >> 5, oc = bid & 31;
    __shared__ int   idx_s[1024];
    __shared__ float ct[32*256];
    __shared__ float fred[256];
    int t = threadIdx.x;

    if (bid == 0) {   // fused finalize: loss + perplexity
        float em = (float)g_counts[t] / (float)NPIX;
        fred[t] = em * logf(em + 1e-10f);
        __syncthreads();
        for (int st = 128; st > 0; st >>= 1) { if (t < st) fred[t] += fred[t+st]; __syncthreads(); }
        if (t == 0) {
            out[LOSS_OFF] = 1.25f * g_loss_sum / (float)OUT_ELEMS;
            out[PERP_OFF] = expf(-fred[0]);
        }
    }

    #pragma unroll
    for (int r = 0; r < 4; r++) idx_s[t + 256*r] = g_idx[b*1024 + t + 256*r];
    const float4* src = (const float4*)(g_code_out + (size_t)oc*32*NE);
    float4* dst = (float4*)ct;
    #pragma unroll
    for (int r = 0; r < 8; r++) dst[t + 256*r] = src[t + 256*r];
    __syncthreads();
    int warp = t >> 5, lane = t & 31;
    float* ob = out + (size_t)b*(CC*HH*WW) + (size_t)oc*32*(HH*WW);
    #pragma unroll
    for (int q = 0; q < 4; q++) {
        int o = warp*4 + q;
        const float* crow = &ct[o*NE];
        #pragma unroll
        for (int p0 = 0; p0 < 1024; p0 += 128) {
            int4 j4 = *(const int4*)&idx_s[p0 + lane*4];
            float4 v;
            v.x = crow[j4.x]; v.y = crow[j4.y]; v.z = crow[j4.z]; v.w = crow[j4.w];
            *(float4*)&ob[(size_t)o*(HH*WW) + p0 + lane*4] = v;
        }
    }
}

// ---------------------------------------------------------------------------
// Launch: fork k_codeout onto a side stream, join before k_scatter.
// ---------------------------------------------------------------------------
extern "C" void kernel_launch(void* const* d_in, const int* in_sizes, int n_in,
                              void* d_out, int out_size) {
    const float* z      = (const float*)d_in[0];
    const float* emb    = (const float*)d_in[1];
    const float* conv_w = (const float*)d_in[2];
    const float* conv_b = (const float*)d_in[3];
    float* out = (float*)d_out;

    static cudaStream_t s_side = 0;
    static cudaEvent_t  ev_fork = 0, ev_join = 0;
    if (s_side == 0) {
        cudaStreamCreateWithFlags(&s_side, cudaStreamNonBlocking);
        cudaEventCreateWithFlags(&ev_fork, cudaEventDisableTiming);
        cudaEventCreateWithFlags(&ev_join, cudaEventDisableTiming);
        cudaFuncSetAttribute(k_argmin_tc, cudaFuncAttributeMaxDynamicSharedMemorySize, DYN_SMEM);
    }

    cudaEventRecord(ev_fork, 0);
    cudaStreamWaitEvent(s_side, ev_fork, 0);

    k_codeout<<<dim3(CC/64, NE/64), 256, 0, s_side>>>(emb, conv_w, conv_b);
    cudaEventRecord(ev_join, s_side);

    k_prep<<<NE, 256>>>(emb);
    k_argmin_tc<<<NPIX/128, 512, DYN_SMEM>>>(z, out);

    cudaStreamWaitEvent(0, ev_join, 0);
    k_scatter<<<BB*HH, 256>>>(out);
}